// round 1
// baseline (speedup 1.0000x reference)
#include <cuda_runtime.h>

// Inputs (metadata order):
//   d_in[0] t_inters : float32 [B, N, 2]   (B=4096, N=128)
//   d_in[1] weights  : float32 [B, N]
//   d_in[2] t_near   : float32 [B, 1]
//   d_in[3] t_far    : float32 [B, 1]
// Output: float32 [B]
//
// Math (u_i sorted ascending since t_bounds is sorted):
//   s(t)   = (t - near) / (far - near)
//   u_i    = 0.5*(s(start_i) + s(end_i))
//   ds_i   = s(end_i) - s(start_i)
//   loss   = 2 * sum_i w_i * (u_i * W_{<i} - S_{<i})  +  (1/3) * sum_i w_i^2 * ds_i
// where W_{<i} = sum_{j<i} w_j, S_{<i} = sum_{j<i} w_j u_j.

__global__ __launch_bounds__(256, 8)
void distor_value_kernel(const float* __restrict__ t_inters,
                         const float* __restrict__ weights,
                         const float* __restrict__ t_near,
                         const float* __restrict__ t_far,
                         float* __restrict__ out,
                         int B) {
    const int warp = (int)((blockIdx.x * blockDim.x + threadIdx.x) >> 5);
    const int lane = (int)(threadIdx.x & 31);
    if (warp >= B) return;

    const float nearv = t_near[warp];
    const float inv   = 1.0f / (t_far[warp] - nearv);

    // Each lane owns 4 consecutive samples: idx = lane*4 + k, k in [0,4)
    // t_inters row = 256 floats; lane reads floats [lane*8, lane*8+8) = 2x float4.
    const float4* ti = reinterpret_cast<const float4*>(t_inters + (size_t)warp * 256);
    const float4  a  = ti[lane * 2 + 0];   // (start0, end0, start1, end1)
    const float4  b  = ti[lane * 2 + 1];   // (start2, end2, start3, end3)
    const float4  w4 = reinterpret_cast<const float4*>(weights + (size_t)warp * 128)[lane];

    float u[4], ds[4], wv[4];
    u[0]  = ((a.x + a.y) * 0.5f - nearv) * inv;  ds[0] = (a.y - a.x) * inv;
    u[1]  = ((a.z + a.w) * 0.5f - nearv) * inv;  ds[1] = (a.w - a.z) * inv;
    u[2]  = ((b.x + b.y) * 0.5f - nearv) * inv;  ds[2] = (b.y - b.x) * inv;
    u[3]  = ((b.z + b.w) * 0.5f - nearv) * inv;  ds[3] = (b.w - b.z) * inv;
    wv[0] = w4.x; wv[1] = w4.y; wv[2] = w4.z; wv[3] = w4.w;

    // Lane-local totals for the scan.
    float Wloc = wv[0] + wv[1] + wv[2] + wv[3];
    float Sloc = wv[0] * u[0] + wv[1] * u[1] + wv[2] * u[2] + wv[3] * u[3];

    // Warp inclusive scan over lane totals, then convert to exclusive base.
    float Winc = Wloc, Sinc = Sloc;
    #pragma unroll
    for (int off = 1; off < 32; off <<= 1) {
        float wUp = __shfl_up_sync(0xFFFFFFFFu, Winc, off);
        float sUp = __shfl_up_sync(0xFFFFFFFFu, Sinc, off);
        if (lane >= off) { Winc += wUp; Sinc += sUp; }
    }
    float Wr = Winc - Wloc;   // exclusive prefix of w at this lane's first element
    float Sr = Sinc - Sloc;   // exclusive prefix of w*u

    // Per-element contribution with running in-lane prefix.
    float loss = 0.0f;
    #pragma unroll
    for (int k = 0; k < 4; k++) {
        loss = fmaf(2.0f * wv[k], fmaf(u[k], Wr, -Sr), loss);
        loss = fmaf(wv[k] * wv[k] * (1.0f / 3.0f), ds[k], loss);
        Wr += wv[k];
        Sr  = fmaf(wv[k], u[k], Sr);
    }

    // Warp butterfly reduction.
    #pragma unroll
    for (int off = 16; off > 0; off >>= 1)
        loss += __shfl_xor_sync(0xFFFFFFFFu, loss, off);

    if (lane == 0) out[warp] = loss;
}

extern "C" void kernel_launch(void* const* d_in, const int* in_sizes, int n_in,
                              void* d_out, int out_size) {
    const float* t_inters = (const float*)d_in[0];
    const float* weights  = (const float*)d_in[1];
    const float* t_near   = (const float*)d_in[2];
    const float* t_far    = (const float*)d_in[3];
    float* out = (float*)d_out;

    const int B = out_size;              // 4096 rows, one warp per row
    const int threads = 256;             // 8 warps per block
    const int blocks  = (B * 32 + threads - 1) / threads;  // 512
    distor_value_kernel<<<blocks, threads>>>(t_inters, weights, t_near, t_far, out, B);
}

// round 2
// speedup vs baseline: 1.0386x; 1.0386x over previous
#include <cuda_runtime.h>

// Inputs (metadata order):
//   d_in[0] t_inters : float32 [B, N, 2]   (B=4096, N=128)
//   d_in[1] weights  : float32 [B, N]
//   d_in[2] t_near   : float32 [B, 1]
//   d_in[3] t_far    : float32 [B, 1]
// Output: float32 [B]
//
// Sorted u_i identity:
//   loss = 2*sum_i w_i*(u_i*W_{<i} - S_{<i}) + (1/3)*sum_i w_i^2*ds_i
// Layout: 2 rows per warp. Lanes [0,16) -> row0, lanes [16,32) -> row1.
// Each lane owns 8 consecutive samples; width-16 segmented shuffles.

__global__ __launch_bounds__(256, 4)
void distor_value_kernel(const float* __restrict__ t_inters,
                         const float* __restrict__ weights,
                         const float* __restrict__ t_near,
                         const float* __restrict__ t_far,
                         float* __restrict__ out,
                         int B) {
    const int warp = (int)((blockIdx.x * blockDim.x + threadIdx.x) >> 5);
    const int lane = (int)(threadIdx.x & 31);
    const int sub  = lane & 15;                 // lane within 16-wide segment
    int row        = warp * 2 + (lane >> 4);

    if (warp * 2 >= B) return;                  // whole warp out of range
    const bool valid = (row < B);
    if (!valid) row = B - 1;                    // clamp for safe loads

    const float nearv = t_near[row];
    const float inv   = 1.0f / (t_far[row] - nearv);
    const float nh    = nearv * inv;            // fold: s = t*inv - nh

    // 6 independent 128-bit loads issued up front (MLP=6).
    const float4* ti = reinterpret_cast<const float4*>(t_inters) + (size_t)row * 64;
    const float4  a0 = ti[sub * 4 + 0];         // samples sub*8+0, +1
    const float4  a1 = ti[sub * 4 + 1];         // +2, +3
    const float4  a2 = ti[sub * 4 + 2];         // +4, +5
    const float4  a3 = ti[sub * 4 + 3];         // +6, +7
    const float4* wp = reinterpret_cast<const float4*>(weights) + (size_t)row * 32;
    const float4  w0 = wp[sub * 2 + 0];
    const float4  w1 = wp[sub * 2 + 1];

    float u[8], dsv[8], wv[8];
    u[0] = fmaf((a0.x + a0.y), 0.5f * inv, -nh);  dsv[0] = (a0.y - a0.x) * inv;
    u[1] = fmaf((a0.z + a0.w), 0.5f * inv, -nh);  dsv[1] = (a0.w - a0.z) * inv;
    u[2] = fmaf((a1.x + a1.y), 0.5f * inv, -nh);  dsv[2] = (a1.y - a1.x) * inv;
    u[3] = fmaf((a1.z + a1.w), 0.5f * inv, -nh);  dsv[3] = (a1.w - a1.z) * inv;
    u[4] = fmaf((a2.x + a2.y), 0.5f * inv, -nh);  dsv[4] = (a2.y - a2.x) * inv;
    u[5] = fmaf((a2.z + a2.w), 0.5f * inv, -nh);  dsv[5] = (a2.w - a2.z) * inv;
    u[6] = fmaf((a3.x + a3.y), 0.5f * inv, -nh);  dsv[6] = (a3.y - a3.x) * inv;
    u[7] = fmaf((a3.z + a3.w), 0.5f * inv, -nh);  dsv[7] = (a3.w - a3.z) * inv;
    wv[0] = w0.x; wv[1] = w0.y; wv[2] = w0.z; wv[3] = w0.w;
    wv[4] = w1.x; wv[5] = w1.y; wv[6] = w1.z; wv[7] = w1.w;

    // Lane-local totals.
    float Wloc = 0.0f, Sloc = 0.0f;
    #pragma unroll
    for (int k = 0; k < 8; k++) {
        Wloc += wv[k];
        Sloc  = fmaf(wv[k], u[k], Sloc);
    }

    // Width-16 segmented inclusive scan (4 steps).
    float Winc = Wloc, Sinc = Sloc;
    #pragma unroll
    for (int off = 1; off < 16; off <<= 1) {
        float wUp = __shfl_up_sync(0xFFFFFFFFu, Winc, off, 16);
        float sUp = __shfl_up_sync(0xFFFFFFFFu, Sinc, off, 16);
        if (sub >= off) { Winc += wUp; Sinc += sUp; }
    }
    float Wr = Winc - Wloc;   // exclusive prefix of w
    float Sr = Sinc - Sloc;   // exclusive prefix of w*u

    // Per-element contributions with running in-lane prefix.
    float loss = 0.0f;
    #pragma unroll
    for (int k = 0; k < 8; k++) {
        loss = fmaf(2.0f * wv[k], fmaf(u[k], Wr, -Sr), loss);
        loss = fmaf(wv[k] * wv[k] * (1.0f / 3.0f), dsv[k], loss);
        Wr += wv[k];
        Sr  = fmaf(wv[k], u[k], Sr);
    }

    // Width-16 segmented butterfly reduction (4 steps).
    #pragma unroll
    for (int off = 8; off > 0; off >>= 1)
        loss += __shfl_xor_sync(0xFFFFFFFFu, loss, off, 16);

    if (valid && sub == 0) out[row] = loss;
}

extern "C" void kernel_launch(void* const* d_in, const int* in_sizes, int n_in,
                              void* d_out, int out_size) {
    const float* t_inters = (const float*)d_in[0];
    const float* weights  = (const float*)d_in[1];
    const float* t_near   = (const float*)d_in[2];
    const float* t_far    = (const float*)d_in[3];
    float* out = (float*)d_out;

    const int B = out_size;                       // 4096 rows, 2 rows per warp
    const int warps   = (B + 1) / 2;              // 2048
    const int threads = 256;                      // 8 warps per CTA
    const int blocks  = (warps * 32 + threads - 1) / threads;  // 256
    distor_value_kernel<<<blocks, threads>>>(t_inters, weights, t_near, t_far, out, B);
}